// round 9
// baseline (speedup 1.0000x reference)
#include <cuda_runtime.h>
#include <cuda_bf16.h>

// Problem shape (fixed by the dataset)
#define BATCH 128
#define SEQLEN 1024
#define TAG 128
#define MID 512   // forward: steps 1..512 -> alpha_512 ; backward: 1023..513 -> beta_512

// Scratch (allocation-free rule: __device__ globals)
__device__ float g_red[BATCH];   // per-batch (logZ - score)

// ---------------- packed f32x2 helpers (Blackwell FFMA2) ----------------
__device__ __forceinline__ unsigned long long pack_f32x2(float lo, float hi) {
    unsigned long long r;
    asm("mov.b64 %0, {%1, %2};" : "=l"(r) : "f"(lo), "f"(hi));
    return r;
}
__device__ __forceinline__ void unpack_f32x2(float& lo, float& hi, unsigned long long v) {
    asm("mov.b64 {%0, %1}, %2;" : "=f"(lo), "=f"(hi) : "l"(v));
}
__device__ __forceinline__ unsigned long long fma2(unsigned long long a,
                                                   unsigned long long b,
                                                   unsigned long long c) {
    unsigned long long d;
    asm("fma.rn.f32x2 %0, %1, %2, %3;" : "=l"(d) : "l"(a), "l"(b), "l"(c));
    return d;
}
__device__ __forceinline__ unsigned long long add2(unsigned long long a,
                                                   unsigned long long b) {
    unsigned long long d;
    asm("add.rn.f32x2 %0, %1, %2;" : "=l"(d) : "l"(a), "l"(b));
    return d;
}

// Named barrier over one 128-thread half (fwd id=1, bwd id=2).
__device__ __forceinline__ void hbar(int id) {
    asm volatile("bar.sync %0, %1;" :: "r"(id), "r"(128) : "memory");
}

// ---- split-u spread: warp w, over u in [32w,32w+32), computes partial sums
// for outputs t = 4l..4l+3 and stores one STS.128. 8 accumulator chains of
// depth 8 (32 cyc) instead of 4x16.
__device__ __forceinline__ void spread(
    const float* __restrict__ vec32,             // own-warp alpha slice (16B aligned)
    const unsigned long long (&ea2)[64],         // [j*16+k]: EA over (u0+2k,u0+2k+1), output j
    float* __restrict__ part, int w, int l)
{
    unsigned long long a0 = 0ull, a1 = 0ull, a2 = 0ull, a3 = 0ull;
    unsigned long long b0 = 0ull, b1 = 0ull, b2 = 0ull, b3 = 0ull;
    const ulonglong2* pp = reinterpret_cast<const ulonglong2*>(vec32);
#pragma unroll
    for (int c = 0; c < 8; c += 2) {
        ulonglong2 v = pp[c];
        a0 = fma2(v.x, ea2[0 * 16 + 2 * c], a0); a0 = fma2(v.y, ea2[0 * 16 + 2 * c + 1], a0);
        a1 = fma2(v.x, ea2[1 * 16 + 2 * c], a1); a1 = fma2(v.y, ea2[1 * 16 + 2 * c + 1], a1);
        a2 = fma2(v.x, ea2[2 * 16 + 2 * c], a2); a2 = fma2(v.y, ea2[2 * 16 + 2 * c + 1], a2);
        a3 = fma2(v.x, ea2[3 * 16 + 2 * c], a3); a3 = fma2(v.y, ea2[3 * 16 + 2 * c + 1], a3);
        ulonglong2 u = pp[c + 1];
        b0 = fma2(u.x, ea2[0 * 16 + 2 * c + 2], b0); b0 = fma2(u.y, ea2[0 * 16 + 2 * c + 3], b0);
        b1 = fma2(u.x, ea2[1 * 16 + 2 * c + 2], b1); b1 = fma2(u.y, ea2[1 * 16 + 2 * c + 3], b1);
        b2 = fma2(u.x, ea2[2 * 16 + 2 * c + 2], b2); b2 = fma2(u.y, ea2[2 * 16 + 2 * c + 3], b2);
        b3 = fma2(u.x, ea2[3 * 16 + 2 * c + 2], b3); b3 = fma2(u.y, ea2[3 * 16 + 2 * c + 3], b3);
    }
    a0 = add2(a0, b0); a1 = add2(a1, b1); a2 = add2(a2, b2); a3 = add2(a3, b3);
    float4 po;
    float lo, hi;
    unpack_f32x2(lo, hi, a0); po.x = lo + hi;
    unpack_f32x2(lo, hi, a1); po.y = lo + hi;
    unpack_f32x2(lo, hi, a2); po.z = lo + hi;
    unpack_f32x2(lo, hi, a3); po.w = lo + hi;
    *reinterpret_cast<float4*>(part + w * TAG + 4 * l) = po;
}

// ---------------- forward step: alpha = m ? (EA^T alpha)*ey : alpha --------
// ONE named barrier per step: partials cross warps through part[BUF] (double
// buffered), while the alpha handoff to the next spread is warp-internal
// (warp w owns outputs AND u-range [32w,32w+32)) -> STS.32 + __syncwarp.
template <int SLOT, int BUF, bool RENORM, bool PREP>
__device__ __forceinline__ void fwd_step(
    int i, int w, int l, int t, float& alpha, int& kacc,
    float (&eyp)[4], float (&mr)[4],
    const float* __restrict__ yprow, const float* __restrict__ mrow,
    const unsigned long long (&ea2)[64],
    float* __restrict__ asmv, float* __restrict__ partb, float* __restrict__ sb)
{
    float* part = partb + BUF * 4 * TAG;
    spread(asmv + 32 * w, ea2, part, w, l);
    hbar(1);

    float invc;
    if (RENORM) {  // repr published at the PREP step; any power of 2 is exact
        int kb = (__float_as_int(sb[0]) >> 23) & 0xff;
        invc = __int_as_float((254 - kb) << 23);
        kacc += 127 - kb;
    }

    // prefetch step i+4's ey/mask (off the serial chain)
    float ey_n = 0.0f, m_n = 1.0f;
    if (i + 4 <= MID) {
        ey_n = __expf(__ldg(yprow + (i + 4) * TAG));
        m_n  = __ldg(mrow + (i + 4));
    }

    float s = (part[t] + part[TAG + t]) + (part[2 * TAG + t] + part[3 * TAG + t]);
    if (RENORM) {
        alpha = ((mr[SLOT] > 0.5f) ? s * eyp[SLOT] : alpha) * invc;
    } else {
        alpha = (mr[SLOT] > 0.5f) ? s * eyp[SLOT] : alpha;
    }
    asmv[t] = alpha;
    if (PREP && t == 0) sb[0] = alpha;
    eyp[SLOT] = ey_n;
    mr[SLOT]  = m_n;
    __syncwarp();
}

// ---------------- backward step: beta = m ? EA@(ey_i*beta) : beta ----------
// register c = ey_i * beta_i is the published/spread vector; slot holds
// (mask_i, ey_pub_i = exp(yp_{i-1}); 1 when i-1 == MID).
template <int SLOT, int BUF, bool RENORM, bool PREP>
__device__ __forceinline__ void bwd_step(
    int i, int w, int l, int t, float& beta, float& c, int& kacc,
    float (&eypub)[4], float (&mr)[4],
    const float* __restrict__ yprow, const float* __restrict__ mrow,
    const unsigned long long (&ea2)[64],
    float* __restrict__ asmv, float* __restrict__ partb, float* __restrict__ sb)
{
    float* part = partb + BUF * 4 * TAG;
    spread(asmv + 32 * w, ea2, part, w, l);
    hbar(2);

    float invc;
    if (RENORM) {
        int kb = (__float_as_int(sb[0]) >> 23) & 0xff;
        invc = __int_as_float((254 - kb) << 23);
        kacc += 127 - kb;
    }

    // prefetch step i-4's (mask, ey_pub)
    float ey_n = 1.0f, m_n = 1.0f;
    if (i - 4 >= MID + 1) {
        m_n  = __ldg(mrow + (i - 4));
        ey_n = (i - 4 > MID + 1) ? __expf(__ldg(yprow + (i - 5) * TAG)) : 1.0f;
    }

    float s = (part[t] + part[TAG + t]) + (part[2 * TAG + t] + part[3 * TAG + t]);
    if (RENORM) {
        beta = ((mr[SLOT] > 0.5f) ? s : beta) * invc;
    } else {
        beta = (mr[SLOT] > 0.5f) ? s : beta;
    }
    c = beta * eypub[SLOT];
    asmv[t] = c;
    if (PREP && t == 0) sb[0] = c;
    eypub[SLOT] = ey_n;
    mr[SLOT]    = m_n;
    __syncwarp();
}

// ---------------- main kernel: 1 CTA (256 thr) per batch -------------------
__global__ void __launch_bounds__(256, 1)
crf_main_kernel(const float* __restrict__ y_pred,
                const int* __restrict__ y_true32,
                const float* __restrict__ mask,
                const float* __restrict__ A)
{
    const int tid = threadIdx.x;
    const int sub = tid >> 7;            // 0 = forward, 1 = backward
    const int t   = tid & (TAG - 1);
    const int w   = t >> 5;
    const int l   = t & 31;
    const int b   = blockIdx.x;

    __shared__ __align__(16) float s_asm[2][TAG];
    __shared__ __align__(16) float s_part[2][2 * 4 * TAG];  // [sub][buf*4*TAG]
    __shared__ float s_sb[2];
    __shared__ int   s_kacc[2];
    __shared__ float s_logZ;
    __shared__ int   s_is64;

    float* asmv  = s_asm[sub];
    float* partb = s_part[sub];
    float* sb    = &s_sb[sub];

    const float* yprow  = y_pred + (size_t)b * SEQLEN * TAG + t;
    const float* mrow   = mask + (size_t)b * SEQLEN;
    const float* ypbase = y_pred + (size_t)b * SEQLEN * TAG;

    // ---- EA block (32 u x 4 outputs) in 64 packed regs ----
    unsigned long long ea2[64];
    const int u0 = 32 * w;
    if (sub == 0) {
#pragma unroll
        for (int j = 0; j < 4; j++)
#pragma unroll
            for (int k = 0; k < 16; k++) {
                float e0 = __expf(__ldg(A + (u0 + 2 * k)     * TAG + (4 * l + j)));
                float e1 = __expf(__ldg(A + (u0 + 2 * k + 1) * TAG + (4 * l + j)));
                ea2[j * 16 + k] = pack_f32x2(e0, e1);
            }
    } else {
#pragma unroll
        for (int j = 0; j < 4; j++)
#pragma unroll
            for (int k = 0; k < 16; k++) {
                float e0 = __expf(__ldg(A + (4 * l + j) * TAG + (u0 + 2 * k)));
                float e1 = __expf(__ldg(A + (4 * l + j) * TAG + (u0 + 2 * k + 1)));
                ea2[j * 16 + k] = pack_f32x2(e0, e1);
            }
    }

    int kacc = 0;
    float eyp[4], mr[4];

    if (sub == 0) {
        // ================= FORWARD: steps 1..512 =================
        float alpha = __expf(__ldg(yprow));    // alpha_0
        asmv[t] = alpha;
        if (t == 0) sb[0] = alpha;
#pragma unroll
        for (int j = 0; j < 4; j++) {
            eyp[j] = __expf(__ldg(yprow + (1 + j) * TAG));
            mr[j]  = __ldg(mrow + (1 + j));
        }
        __syncwarp();

        for (int i = 1; i <= MID - 3; i += 4) {   // 128 groups
            fwd_step<0, 0, true,  false>(i,     w, l, t, alpha, kacc, eyp, mr, yprow, mrow, ea2, asmv, partb, sb);
            fwd_step<1, 1, false, false>(i + 1, w, l, t, alpha, kacc, eyp, mr, yprow, mrow, ea2, asmv, partb, sb);
            fwd_step<2, 0, false, false>(i + 2, w, l, t, alpha, kacc, eyp, mr, yprow, mrow, ea2, asmv, partb, sb);
            fwd_step<3, 1, false, true >(i + 3, w, l, t, alpha, kacc, eyp, mr, yprow, mrow, ea2, asmv, partb, sb);
        }
        if (t == 0) s_kacc[0] = kacc;
        // asmv holds alpha_512
    } else {
        // ================= BACKWARD: steps 1023..513 =================
        float beta = 1.0f;
        float c = __expf(__ldg(yprow + (SEQLEN - 1) * TAG));   // c_1023
        asmv[t] = c;
        if (t == 0) sb[0] = c;
#pragma unroll
        for (int j = 0; j < 4; j++) {
            mr[j]  = __ldg(mrow + (SEQLEN - 1 - j));
            eyp[j] = __expf(__ldg(yprow + (SEQLEN - 2 - j) * TAG));
        }
        __syncwarp();

        for (int i = SEQLEN - 1; i >= MID + 7; i -= 4) {   // 127 groups: 1023..516
            bwd_step<0, 0, true,  false>(i,     w, l, t, beta, c, kacc, eyp, mr, yprow, mrow, ea2, asmv, partb, sb);
            bwd_step<1, 1, false, false>(i - 1, w, l, t, beta, c, kacc, eyp, mr, yprow, mrow, ea2, asmv, partb, sb);
            bwd_step<2, 0, false, false>(i - 2, w, l, t, beta, c, kacc, eyp, mr, yprow, mrow, ea2, asmv, partb, sb);
            bwd_step<3, 1, false, true >(i - 3, w, l, t, beta, c, kacc, eyp, mr, yprow, mrow, ea2, asmv, partb, sb);
        }
        // remainder: steps 515, 514, 513
        bwd_step<0, 0, true,  false>(MID + 3, w, l, t, beta, c, kacc, eyp, mr, yprow, mrow, ea2, asmv, partb, sb);
        bwd_step<1, 1, false, false>(MID + 2, w, l, t, beta, c, kacc, eyp, mr, yprow, mrow, ea2, asmv, partb, sb);
        bwd_step<2, 0, false, false>(MID + 1, w, l, t, beta, c, kacc, eyp, mr, yprow, mrow, ea2, asmv, partb, sb);
        if (t == 0) s_kacc[1] = kacc;
        // asmv holds beta_512 (ey_pub of step 513 is 1)
    }

    __syncthreads();   // join halves

    // ---- logZ = log(sum_t a_mid[t]*b_mid[t]) - (kf+kb)*ln2 ----
    if (tid < 32) {
        float v = 0.0f;
#pragma unroll
        for (int j = 0; j < 4; j++)
            v += s_asm[0][tid + 32 * j] * s_asm[1][tid + 32 * j];
#pragma unroll
        for (int o = 16; o > 0; o >>= 1)
            v += __shfl_xor_sync(0xffffffffu, v, o);
        if (tid == 0)
            s_logZ = logf(v) - (float)(s_kacc[0] + s_kacc[1]) * 0.69314718055994530942f;
    }

    // ---- path score (fused) ----
    // y_true is int32 under JAX default x64-disabled; detect genuine LE int64
    // (odd words of first 128 entries all zero <=> int64; tags are 0..127).
    if (tid == 0) s_is64 = 1;
    __syncthreads();
    if (tid < 128 && y_true32[2 * tid + 1] != 0) s_is64 = 0;
    __syncthreads();
    const int stride = s_is64 ? 2 : 1;
    const int* yt = y_true32 + (size_t)b * SEQLEN * stride;

    float acc = 0.0f;
    for (int s = tid; s < SEQLEN; s += 256) {
        int tag = yt[s * stride] & (TAG - 1);
        float m = mrow[s];
        acc += ypbase[(size_t)s * TAG + tag] * m;
        if (s + 1 < SEQLEN) {
            int tag2 = yt[(s + 1) * stride] & (TAG - 1);
            acc += A[tag * TAG + tag2] * m * mrow[s + 1];
        }
    }
    float* red = &s_part[0][0];   // scratch (scan done)
    red[tid] = acc;
    __syncthreads();
    if (tid < 32) {
        float v = 0.0f;
#pragma unroll
        for (int j = 0; j < 8; j++) v += red[tid + 32 * j];
#pragma unroll
        for (int o = 16; o > 0; o >>= 1)
            v += __shfl_xor_sync(0xffffffffu, v, o);
        if (tid == 0) g_red[b] = s_logZ - v;
    }
}

// ---------------- final mean kernel ----------------
__global__ void __launch_bounds__(128, 1)
crf_final_kernel(float* __restrict__ out)
{
    const int t = threadIdx.x;
    float v = g_red[t];
    __shared__ float red[128];
    red[t] = v;
    __syncthreads();
    if (t < 32) {
        float s = red[t] + red[t + 32] + red[t + 64] + red[t + 96];
#pragma unroll
        for (int o = 16; o > 0; o >>= 1)
            s += __shfl_xor_sync(0xffffffffu, s, o);
        if (t == 0) out[0] = s * (1.0f / (float)BATCH);
    }
}

// ---------------- launch ----------------
extern "C" void kernel_launch(void* const* d_in, const int* in_sizes, int n_in,
                              void* d_out, int out_size)
{
    const float* y_pred = nullptr;
    const float* A = nullptr;
    const int* y_true = nullptr;
    const float* mask = nullptr;
    for (int i = 0; i < n_in; i++) {
        long long sz = in_sizes[i];
        if (sz == (long long)BATCH * SEQLEN * TAG) {
            y_pred = (const float*)d_in[i];
        } else if (sz == (long long)TAG * TAG) {
            A = (const float*)d_in[i];
        } else if (sz == (long long)BATCH * SEQLEN) {
            if (!y_true) y_true = (const int*)d_in[i];
            else mask = (const float*)d_in[i];
        }
    }

    crf_main_kernel<<<BATCH, 256>>>(y_pred, y_true, mask, A);
    crf_final_kernel<<<1, 128>>>((float*)d_out);
}

// round 10
// speedup vs baseline: 1.0682x; 1.0682x over previous
#include <cuda_runtime.h>
#include <cuda_bf16.h>

// Problem shape (fixed by the dataset)
#define BATCH 128
#define SEQLEN 1024
#define TAG 128
#define MID 512   // forward: steps 1..512 -> alpha_512 ; backward: 1023..513 -> beta_512

// Scratch (allocation-free rule: __device__ globals)
__device__ float g_red[BATCH];   // per-batch (logZ - score)

// ---------------- packed f32x2 helpers (Blackwell FFMA2) ----------------
__device__ __forceinline__ unsigned long long pack_f32x2(float lo, float hi) {
    unsigned long long r;
    asm("mov.b64 %0, {%1, %2};" : "=l"(r) : "f"(lo), "f"(hi));
    return r;
}
__device__ __forceinline__ void unpack_f32x2(float& lo, float& hi, unsigned long long v) {
    asm("mov.b64 {%0, %1}, %2;" : "=f"(lo), "=f"(hi) : "l"(v));
}
__device__ __forceinline__ unsigned long long fma2(unsigned long long a,
                                                   unsigned long long b,
                                                   unsigned long long c) {
    unsigned long long d;
    asm("fma.rn.f32x2 %0, %1, %2, %3;" : "=l"(d) : "l"(a), "l"(b), "l"(c));
    return d;
}
__device__ __forceinline__ unsigned long long add2(unsigned long long a,
                                                   unsigned long long b) {
    unsigned long long d;
    asm("add.rn.f32x2 %0, %1, %2;" : "=l"(d) : "l"(a), "l"(b));
    return d;
}

// Named barrier over one 128-thread half (fwd id=1, bwd id=2).
__device__ __forceinline__ void hbar(int id) {
    asm volatile("bar.sync %0, %1;" :: "r"(id), "r"(128) : "memory");
}

// ---- split-u spread: warp w, over u in [32w,32w+32), computes partial sums
// for outputs t = 4l..4l+3 and stores one STS.128. 8 accumulator chains.
__device__ __forceinline__ void spread(
    const float* __restrict__ vec32,             // own-warp alpha slice (16B aligned)
    const unsigned long long (&ea2)[64],         // [j*16+k]: EA over (u0+2k,u0+2k+1), output j
    float* __restrict__ part, int w, int l)
{
    unsigned long long a0 = 0ull, a1 = 0ull, a2 = 0ull, a3 = 0ull;
    unsigned long long b0 = 0ull, b1 = 0ull, b2 = 0ull, b3 = 0ull;
    const ulonglong2* pp = reinterpret_cast<const ulonglong2*>(vec32);
#pragma unroll
    for (int c = 0; c < 8; c += 2) {
        ulonglong2 v = pp[c];
        a0 = fma2(v.x, ea2[0 * 16 + 2 * c], a0); a0 = fma2(v.y, ea2[0 * 16 + 2 * c + 1], a0);
        a1 = fma2(v.x, ea2[1 * 16 + 2 * c], a1); a1 = fma2(v.y, ea2[1 * 16 + 2 * c + 1], a1);
        a2 = fma2(v.x, ea2[2 * 16 + 2 * c], a2); a2 = fma2(v.y, ea2[2 * 16 + 2 * c + 1], a2);
        a3 = fma2(v.x, ea2[3 * 16 + 2 * c], a3); a3 = fma2(v.y, ea2[3 * 16 + 2 * c + 1], a3);
        ulonglong2 u = pp[c + 1];
        b0 = fma2(u.x, ea2[0 * 16 + 2 * c + 2], b0); b0 = fma2(u.y, ea2[0 * 16 + 2 * c + 3], b0);
        b1 = fma2(u.x, ea2[1 * 16 + 2 * c + 2], b1); b1 = fma2(u.y, ea2[1 * 16 + 2 * c + 3], b1);
        b2 = fma2(u.x, ea2[2 * 16 + 2 * c + 2], b2); b2 = fma2(u.y, ea2[2 * 16 + 2 * c + 3], b2);
        b3 = fma2(u.x, ea2[3 * 16 + 2 * c + 2], b3); b3 = fma2(u.y, ea2[3 * 16 + 2 * c + 3], b3);
    }
    a0 = add2(a0, b0); a1 = add2(a1, b1); a2 = add2(a2, b2); a3 = add2(a3, b3);
    float4 po;
    float lo, hi;
    unpack_f32x2(lo, hi, a0); po.x = lo + hi;
    unpack_f32x2(lo, hi, a1); po.y = lo + hi;
    unpack_f32x2(lo, hi, a2); po.z = lo + hi;
    unpack_f32x2(lo, hi, a3); po.w = lo + hi;
    *reinterpret_cast<float4*>(part + w * TAG + 4 * l) = po;
}

// ---------------- forward step: alpha = m ? (EA^T alpha)*ey : alpha --------
// One named barrier per step; alpha handoff is warp-internal (STS.32 +
// __syncwarp). Prefetch LDGs issued FIRST so their latency stays off the
// post-barrier critical window.
template <int SLOT, int BUF, bool RENORM, bool PREP>
__device__ __forceinline__ void fwd_step(
    int i, int w, int l, int t, float& alpha, int& kacc,
    float (&eyp)[4], float (&mr)[4],
    const float* __restrict__ yprow, const float* __restrict__ mrow,
    const unsigned long long (&ea2)[64],
    float* __restrict__ asmv, float* __restrict__ partb, float* __restrict__ sb)
{
    // prefetch step i+4's raw y_pred/mask (exp applied below, off-chain)
    float yp_n = 0.0f, m_n = 1.0f;
    if (i + 4 <= MID) {
        yp_n = __ldg(yprow + (i + 4) * TAG);
        m_n  = __ldg(mrow + (i + 4));
    }

    float* part = partb + BUF * 4 * TAG;
    spread(asmv + 32 * w, ea2, part, w, l);
    hbar(1);

    float invc;
    if (RENORM) {  // repr published at the PREP step; power-of-2 scale is exact
        int kb = (__float_as_int(sb[0]) >> 23) & 0xff;
        invc = __int_as_float((254 - kb) << 23);
        kacc += 127 - kb;
    }

    float s = (part[t] + part[TAG + t]) + (part[2 * TAG + t] + part[3 * TAG + t]);
    if (RENORM) {
        alpha = ((mr[SLOT] > 0.5f) ? s * eyp[SLOT] : alpha) * invc;
    } else {
        alpha = (mr[SLOT] > 0.5f) ? s * eyp[SLOT] : alpha;
    }
    asmv[t] = alpha;
    if (PREP && t == 0) sb[0] = alpha;
    eyp[SLOT] = (i + 4 <= MID) ? __expf(yp_n) : 0.0f;
    mr[SLOT]  = m_n;
    __syncwarp();
}

// ---------------- backward step: beta = m ? EA@(ey_i*beta) : beta ----------
template <int SLOT, int BUF, bool RENORM, bool PREP>
__device__ __forceinline__ void bwd_step(
    int i, int w, int l, int t, float& beta, float& c, int& kacc,
    float (&eypub)[4], float (&mr)[4],
    const float* __restrict__ yprow, const float* __restrict__ mrow,
    const unsigned long long (&ea2)[64],
    float* __restrict__ asmv, float* __restrict__ partb, float* __restrict__ sb)
{
    // prefetch step i-4's raw (mask, y_pred for ey_pub)
    float yp_n = 0.0f, m_n = 1.0f;
    bool pf = (i - 4 >= MID + 1);
    bool pfe = (i - 4 > MID + 1);
    if (pf) {
        m_n = __ldg(mrow + (i - 4));
        if (pfe) yp_n = __ldg(yprow + (i - 5) * TAG);
    }

    float* part = partb + BUF * 4 * TAG;
    spread(asmv + 32 * w, ea2, part, w, l);
    hbar(2);

    float invc;
    if (RENORM) {
        int kb = (__float_as_int(sb[0]) >> 23) & 0xff;
        invc = __int_as_float((254 - kb) << 23);
        kacc += 127 - kb;
    }

    float s = (part[t] + part[TAG + t]) + (part[2 * TAG + t] + part[3 * TAG + t]);
    if (RENORM) {
        beta = ((mr[SLOT] > 0.5f) ? s : beta) * invc;
    } else {
        beta = (mr[SLOT] > 0.5f) ? s : beta;
    }
    c = beta * eypub[SLOT];
    asmv[t] = c;
    if (PREP && t == 0) sb[0] = c;
    eypub[SLOT] = pfe ? __expf(yp_n) : 1.0f;
    mr[SLOT]    = m_n;
    __syncwarp();
}

// ---------------- main kernel: 1 CTA (256 thr) per batch -------------------
__global__ void __launch_bounds__(256, 1)
crf_main_kernel(const float* __restrict__ y_pred,
                const int* __restrict__ y_true32,
                const float* __restrict__ mask,
                const float* __restrict__ A)
{
    const int tid = threadIdx.x;
    const int sub = tid >> 7;            // 0 = forward, 1 = backward
    const int t   = tid & (TAG - 1);
    const int w   = t >> 5;
    const int l   = t & 31;
    const int b   = blockIdx.x;

    __shared__ __align__(16) float s_asm[2][TAG];
    __shared__ __align__(16) float s_part[2][2 * 4 * TAG];  // [sub][buf*4*TAG]
    __shared__ float s_sb[2];
    __shared__ int   s_kacc[2];
    __shared__ float s_logZ;
    __shared__ int   s_is64;

    float* asmv  = s_asm[sub];
    float* partb = s_part[sub];
    float* sb    = &s_sb[sub];

    const float* yprow  = y_pred + (size_t)b * SEQLEN * TAG + t;
    const float* mrow   = mask + (size_t)b * SEQLEN;
    const float* ypbase = y_pred + (size_t)b * SEQLEN * TAG;

    // ---- EA block (32 u x 4 outputs) in 64 packed regs ----
    unsigned long long ea2[64];
    const int u0 = 32 * w;
    if (sub == 0) {
#pragma unroll
        for (int j = 0; j < 4; j++)
#pragma unroll
            for (int k = 0; k < 16; k++) {
                float e0 = __expf(__ldg(A + (u0 + 2 * k)     * TAG + (4 * l + j)));
                float e1 = __expf(__ldg(A + (u0 + 2 * k + 1) * TAG + (4 * l + j)));
                ea2[j * 16 + k] = pack_f32x2(e0, e1);
            }
    } else {
#pragma unroll
        for (int j = 0; j < 4; j++)
#pragma unroll
            for (int k = 0; k < 16; k++) {
                float e0 = __expf(__ldg(A + (4 * l + j) * TAG + (u0 + 2 * k)));
                float e1 = __expf(__ldg(A + (4 * l + j) * TAG + (u0 + 2 * k + 1)));
                ea2[j * 16 + k] = pack_f32x2(e0, e1);
            }
    }

    int kacc = 0;
    float eyp[4], mr[4];

    if (sub == 0) {
        // ================= FORWARD: steps 1..512 =================
        float alpha = __expf(__ldg(yprow));    // alpha_0
        asmv[t] = alpha;
        if (t == 0) sb[0] = alpha;
#pragma unroll
        for (int j = 0; j < 4; j++) {
            eyp[j] = __expf(__ldg(yprow + (1 + j) * TAG));
            mr[j]  = __ldg(mrow + (1 + j));
        }
        __syncwarp();

        for (int i = 1; i <= MID - 3; i += 4) {   // 128 groups
            fwd_step<0, 0, true,  false>(i,     w, l, t, alpha, kacc, eyp, mr, yprow, mrow, ea2, asmv, partb, sb);
            fwd_step<1, 1, false, false>(i + 1, w, l, t, alpha, kacc, eyp, mr, yprow, mrow, ea2, asmv, partb, sb);
            fwd_step<2, 0, false, false>(i + 2, w, l, t, alpha, kacc, eyp, mr, yprow, mrow, ea2, asmv, partb, sb);
            fwd_step<3, 1, false, true >(i + 3, w, l, t, alpha, kacc, eyp, mr, yprow, mrow, ea2, asmv, partb, sb);
        }
        if (t == 0) s_kacc[0] = kacc;
        // asmv holds alpha_512
    } else {
        // ================= BACKWARD: steps 1023..513 =================
        float beta = 1.0f;
        float c = __expf(__ldg(yprow + (SEQLEN - 1) * TAG));   // c_1023
        asmv[t] = c;
        if (t == 0) sb[0] = c;
#pragma unroll
        for (int j = 0; j < 4; j++) {
            mr[j]  = __ldg(mrow + (SEQLEN - 1 - j));
            eyp[j] = __expf(__ldg(yprow + (SEQLEN - 2 - j) * TAG));
        }
        __syncwarp();

        // ---- phase-shift: one dummy spread (~half a step of dependent work)
        // so bwd's FFMA bursts land inside fwd's barrier/LDS windows instead
        // of colliding. Junk input (uninitialized buf1) flows only into
        // partial slots that the first real spread overwrites (same thread,
        // same addresses, program-ordered) before any post-hbar read.
        spread(partb + 4 * TAG + 32 * w, ea2, partb, w, l);

        for (int i = SEQLEN - 1; i >= MID + 7; i -= 4) {   // 127 groups: 1023..516
            bwd_step<0, 0, true,  false>(i,     w, l, t, beta, c, kacc, eyp, mr, yprow, mrow, ea2, asmv, partb, sb);
            bwd_step<1, 1, false, false>(i - 1, w, l, t, beta, c, kacc, eyp, mr, yprow, mrow, ea2, asmv, partb, sb);
            bwd_step<2, 0, false, false>(i - 2, w, l, t, beta, c, kacc, eyp, mr, yprow, mrow, ea2, asmv, partb, sb);
            bwd_step<3, 1, false, true >(i - 3, w, l, t, beta, c, kacc, eyp, mr, yprow, mrow, ea2, asmv, partb, sb);
        }
        // remainder: steps 515, 514, 513
        bwd_step<0, 0, true,  false>(MID + 3, w, l, t, beta, c, kacc, eyp, mr, yprow, mrow, ea2, asmv, partb, sb);
        bwd_step<1, 1, false, false>(MID + 2, w, l, t, beta, c, kacc, eyp, mr, yprow, mrow, ea2, asmv, partb, sb);
        bwd_step<2, 0, false, false>(MID + 1, w, l, t, beta, c, kacc, eyp, mr, yprow, mrow, ea2, asmv, partb, sb);
        if (t == 0) s_kacc[1] = kacc;
        // asmv holds beta_512 (ey_pub of step 513 is 1)
    }

    __syncthreads();   // join halves

    // ---- logZ = log(sum_t a_mid[t]*b_mid[t]) - (kf+kb)*ln2 ----
    if (tid < 32) {
        float v = 0.0f;
#pragma unroll
        for (int j = 0; j < 4; j++)
            v += s_asm[0][tid + 32 * j] * s_asm[1][tid + 32 * j];
#pragma unroll
        for (int o = 16; o > 0; o >>= 1)
            v += __shfl_xor_sync(0xffffffffu, v, o);
        if (tid == 0)
            s_logZ = logf(v) - (float)(s_kacc[0] + s_kacc[1]) * 0.69314718055994530942f;
    }

    // ---- path score (fused) ----
    // y_true is int32 under JAX default x64-disabled; detect genuine LE int64
    // (odd words of first 128 entries all zero <=> int64; tags are 0..127).
    if (tid == 0) s_is64 = 1;
    __syncthreads();
    if (tid < 128 && y_true32[2 * tid + 1] != 0) s_is64 = 0;
    __syncthreads();
    const int stride = s_is64 ? 2 : 1;
    const int* yt = y_true32 + (size_t)b * SEQLEN * stride;

    float acc = 0.0f;
    for (int s = tid; s < SEQLEN; s += 256) {
        int tag = yt[s * stride] & (TAG - 1);
        float m = mrow[s];
        acc += ypbase[(size_t)s * TAG + tag] * m;
        if (s + 1 < SEQLEN) {
            int tag2 = yt[(s + 1) * stride] & (TAG - 1);
            acc += A[tag * TAG + tag2] * m * mrow[s + 1];
        }
    }
    float* red = &s_part[0][0];   // scratch (scan done)
    red[tid] = acc;
    __syncthreads();
    if (tid < 32) {
        float v = 0.0f;
#pragma unroll
        for (int j = 0; j < 8; j++) v += red[tid + 32 * j];
#pragma unroll
        for (int o = 16; o > 0; o >>= 1)
            v += __shfl_xor_sync(0xffffffffu, v, o);
        if (tid == 0) g_red[b] = s_logZ - v;
    }
}

// ---------------- final mean kernel ----------------
__global__ void __launch_bounds__(128, 1)
crf_final_kernel(float* __restrict__ out)
{
    const int t = threadIdx.x;
    float v = g_red[t];
    __shared__ float red[128];
    red[t] = v;
    __syncthreads();
    if (t < 32) {
        float s = red[t] + red[t + 32] + red[t + 64] + red[t + 96];
#pragma unroll
        for (int o = 16; o > 0; o >>= 1)
            s += __shfl_xor_sync(0xffffffffu, s, o);
        if (t == 0) out[0] = s * (1.0f / (float)BATCH);
    }
}

// ---------------- launch ----------------
extern "C" void kernel_launch(void* const* d_in, const int* in_sizes, int n_in,
                              void* d_out, int out_size)
{
    const float* y_pred = nullptr;
    const float* A = nullptr;
    const int* y_true = nullptr;
    const float* mask = nullptr;
    for (int i = 0; i < n_in; i++) {
        long long sz = in_sizes[i];
        if (sz == (long long)BATCH * SEQLEN * TAG) {
            y_pred = (const float*)d_in[i];
        } else if (sz == (long long)TAG * TAG) {
            A = (const float*)d_in[i];
        } else if (sz == (long long)BATCH * SEQLEN) {
            if (!y_true) y_true = (const int*)d_in[i];
            else mask = (const float*)d_in[i];
        }
    }

    crf_main_kernel<<<BATCH, 256>>>(y_pred, y_true, mask, A);
    crf_final_kernel<<<1, 128>>>((float*)d_out);
}